// round 6
// baseline (speedup 1.0000x reference)
#include <cuda_runtime.h>
#include <math.h>
#include <stdint.h>

#define B_   32
#define T_   512
#define E_   256
#define H_   512
#define L_   50
#define NT   256
#define NBLK 256     // total recurrent blocks
#define BPG  128     // blocks per batch-group

typedef unsigned long long ull;

// ---------------- device globals -----------------------------------------------
__device__ __align__(16) float g_hT[2 * 2 * H_ * 16];   // [grp][buf][hd][16b]
__device__ __align__(16) float g_Y[T_ * H_ * B_];       // [t][hd][32b]
__device__ __align__(16) float g_Zx[(size_t)T_ * 2048 * B_]; // [t][col][32b]
__device__ float g_acc[B_];
__device__ unsigned g_barc[2];                          // per-group monotonic counters

// ---------------- helpers --------------------------------------------------------
__device__ __forceinline__ ull ffma2_(ull a, ull b, ull c) {
    ull d;
    asm("fma.rn.f32x2 %0, %1, %2, %3;" : "=l"(d) : "l"(a), "l"(b), "l"(c));
    return d;
}
__device__ __forceinline__ ull splat2_(float x) {
    ull r; unsigned xi = __float_as_uint(x);
    asm("mov.b64 %0, {%1, %1};" : "=l"(r) : "r"(xi));
    return r;
}
__device__ __forceinline__ void cp16(uint32_t dst, const void* src) {
    asm volatile("cp.async.cg.shared.global [%0], [%1], 16;" :: "r"(dst), "l"(src));
}
__device__ __forceinline__ void cp_commit() { asm volatile("cp.async.commit_group;"); }
#define CP_WAIT(N) asm volatile("cp.async.wait_group %0;" :: "n"(N) : "memory")

__device__ __forceinline__ float fsig_(float x) {
    x = fminf(fmaxf(x, -30.f), 30.f);
    float e = __expf(-x);
    return __fdividef(1.f, 1.f + e);
}
__device__ __forceinline__ float ftanh_(float x) {
    x = fminf(fmaxf(x, -15.f), 15.f);
    float e = __expf(-2.f * x);
    return __fdividef(1.f - e, 1.f + e);
}

// ================================================================================
// Phase A: zx precompute.  grid = (T_ * 4); also resets barrier counters / acc
// ================================================================================
#define ZXD_OFF  0
#define ZWB_OFF  (256*32)
#define ZX_SMEM  ((8192 + 3*8192) * 4)
#define XT_PAD   261

__global__ void __launch_bounds__(256, 1)
zx_kernel(const int* __restrict__ q, const float* __restrict__ we,
          const float* __restrict__ W, const float* __restrict__ bvec)
{
    extern __shared__ float sm[];
    float* XD = sm + ZXD_OFF;
    float* WB = sm + ZWB_OFF;
    float* XT = sm + ZWB_OFF;
    const uint32_t smu = (uint32_t)__cvta_generic_to_shared(sm);
    __shared__ int qrow[32];

    const int tid = threadIdx.x;
    const int t   = blockIdx.x >> 2;
    const int c0  = (blockIdx.x & 3) << 9;

    if (blockIdx.x == 0) {
        if (tid < 2)  g_barc[tid] = 0u;
        if (tid < 32) g_acc[tid] = 0.f;
    }

    if (tid < 32) qrow[tid] = q[(tid << 9) + t];
    __syncthreads();
    #pragma unroll
    for (int i = 0; i < 32; ++i) {
        int idx = tid + (i << 8);
        int b = idx >> 8, k = idx & 255;
        XT[b * XT_PAD + k] = we[(((size_t)qrow[b]) << 8) + k];
    }
    __syncthreads();
    float xbuf[32];
    #pragma unroll
    for (int i = 0; i < 32; ++i) {
        int idx = tid + (i << 8);
        int k = idx >> 5, b = idx & 31;
        xbuf[i] = XT[b * XT_PAD + k];
    }
    __syncthreads();
    #pragma unroll
    for (int i = 0; i < 32; ++i) {
        int idx = tid + (i << 8);
        int k = idx >> 5, b = idx & 31;
        XD[k * 32 + b] = xbuf[i];
    }
    __syncthreads();

    const int bq = tid & 3;
    const int cq = tid >> 2;

    #pragma unroll
    for (int pc = 0; pc < 2; ++pc) {
        #pragma unroll
        for (int i = 0; i < 8; ++i) {
            int u = tid + (i << 8);
            int kk = u >> 7, c16 = u & 127;
            cp16(smu + (uint32_t)((ZWB_OFF + pc * 8192 + kk * 512 + (c16 << 2)) * 4),
                 W + ((size_t)(pc * 16 + kk)) * 2048 + c0 + (c16 << 2));
        }
        cp_commit();
    }

    ull acc[4][8];
    #pragma unroll
    for (int i = 0; i < 4; ++i)
        #pragma unroll
        for (int j = 0; j < 8; ++j) acc[i][j] = 0ull;

    for (int kc = 0; kc < 16; ++kc) {
        if (kc < 15) { CP_WAIT(1); } else { CP_WAIT(0); }
        __syncthreads();
        const float* Wc = WB + (kc % 3) * 8192;
        const float* Xc = XD + kc * 16 * 32;
        #pragma unroll
        for (int kk = 0; kk < 16; ++kk) {
            ulonglong2 xa = *(const ulonglong2*)(Xc + kk * 32 + bq * 8);
            ulonglong2 xb = *(const ulonglong2*)(Xc + kk * 32 + bq * 8 + 4);
            float4 w0 = *(const float4*)(Wc + kk * 512 + cq * 8);
            float4 w1 = *(const float4*)(Wc + kk * 512 + cq * 8 + 4);
            ull ws[8];
            ws[0] = splat2_(w0.x); ws[1] = splat2_(w0.y);
            ws[2] = splat2_(w0.z); ws[3] = splat2_(w0.w);
            ws[4] = splat2_(w1.x); ws[5] = splat2_(w1.y);
            ws[6] = splat2_(w1.z); ws[7] = splat2_(w1.w);
            #pragma unroll
            for (int c = 0; c < 8; ++c) {
                acc[0][c] = ffma2_(xa.x, ws[c], acc[0][c]);
                acc[1][c] = ffma2_(xa.y, ws[c], acc[1][c]);
                acc[2][c] = ffma2_(xb.x, ws[c], acc[2][c]);
                acc[3][c] = ffma2_(xb.y, ws[c], acc[3][c]);
            }
        }
        if (kc + 2 < 16) {
            int buf = (kc + 2) % 3;
            #pragma unroll
            for (int i = 0; i < 8; ++i) {
                int u = tid + (i << 8);
                int kk = u >> 7, c16 = u & 127;
                cp16(smu + (uint32_t)((ZWB_OFF + buf * 8192 + kk * 512 + (c16 << 2)) * 4),
                     W + ((size_t)((kc + 2) * 16 + kk)) * 2048 + c0 + (c16 << 2));
            }
            cp_commit();
        }
    }

    #pragma unroll
    for (int c = 0; c < 8; ++c) {
        int cg = c0 + cq * 8 + c;
        float bb = __ldg(&bvec[cg]);
        float* outp = g_Zx + ((size_t)t * 2048 + cg) * 32 + bq * 8;
        #pragma unroll
        for (int bp = 0; bp < 4; ++bp) {
            union { ull u; float2 f; } v; v.u = acc[bp][c];
            v.f.x += bb; v.f.y += bb;
            *(float2*)(outp + bp * 2) = v.f;
        }
    }
}

// ================================================================================
// Phase B: recurrence. 256 blocks (2/SM), 2 groups x 128; block = 4 hd x 16 cols x 16 b
// ================================================================================
#define SWH_FLT  0                       // [512 k][16 b] = 8192
#define WD_FLT   8192                    // u64[512 k][16 c] = 16384 floats
#define ZXS_FLT  (WD_FLT + 16384)        // 24576 : [16 c][16 b] = 256
#define ZR_FLT   (ZXS_FLT + 256)         // 24832 : [8 ws][16 c][16 b] = 2048
#define CS_FLT   (ZR_FLT + 2048)         // 26880 : [64]
#define LEN_FLT  (CS_FLT + 64)           // 26944 : [16] ints
#define SMEM_TOTAL ((LEN_FLT + 16) * 4)  // 107840 B

__global__ void __launch_bounds__(NT, 2)
lstm_kernel(const int* __restrict__ lengths, const float* __restrict__ W)
{
    extern __shared__ float sm[];
    float* Swh  = sm + SWH_FLT;
    ull*   WDu  = (ull*)(sm + WD_FLT);
    float* zxs  = sm + ZXS_FLT;
    float* zred = sm + ZR_FLT;
    float* cs   = sm + CS_FLT;
    int*   ls   = (int*)(sm + LEN_FLT);
    const uint32_t smu = (uint32_t)__cvta_generic_to_shared(sm);

    const int tid = threadIdx.x;
    const int bid = blockIdx.x;
    const int grp = bid & 1;             // interleaved groups for SM pairing
    const int gb  = bid >> 1;            // 0..127
    const int hd0 = gb << 2;             // 4 h-dims per block

    // prologue: duplicated W slice (rows 256..767, block's 16 cols), zero state
    for (int i = tid; i < 512 * 16; i += NT) {
        int k = i >> 4, c = i & 15;      // c = gate*4 + jj
        float w = W[((size_t)(256 + k)) * 2048 + (((c >> 2) << 9) + hd0 + (c & 3))];
        WDu[i] = splat2_(w);
    }
    for (int i = tid; i < 512 * 16; i += NT) Swh[i] = 0.f;
    if (tid < 64) cs[tid] = 0.f;
    if (tid < 16) ls[tid] = lengths[(grp << 4) + tid];
    __syncthreads();

    const int wid  = tid >> 5, lane = tid & 31;
    const int bg   = lane & 7;           // batch pair: b = 2bg, 2bg+1
    const int cq   = lane >> 3;          // col quad:  c = 4cq..4cq+3
    const int krow0 = wid << 6;
    const int srow  = lane >> 1, spart = lane & 1;

    unsigned* barp = &g_barc[grp];

    for (int t = 0; t < T_; ++t) {
        const float* hsrc = g_hT + (((grp << 1) + (t & 1)) << 13);

        // ---- issue 4 pipelined cp.async groups (h chunks; zx rides chunk 0) ----
        #pragma unroll
        for (int c = 0; c < 4; ++c) {
            if (t > 0) {
                int r = krow0 + (c << 4) + srow;
                int fo = (r << 4) + (spart << 3);
                cp16(smu + (uint32_t)((SWH_FLT + fo) * 4), hsrc + fo);
                cp16(smu + (uint32_t)((SWH_FLT + fo + 4) * 4), hsrc + fo + 4);
            }
            if (c == 0 && tid < 64) {
                int r = tid >> 2, p = tid & 3;   // col r (0..15), 16B chunk p
                int gcol = ((r >> 2) << 9) + hd0 + (r & 3);
                const float* src = g_Zx + ((size_t)(t << 11) + gcol) * 32
                                   + (grp << 4) + (p << 2);
                cp16(smu + (uint32_t)((ZXS_FLT + (r << 4) + (p << 2)) * 4), src);
            }
            cp_commit();
        }

        // ---- h-GEMM: 4 chunks x 16 rows ----
        ull a0 = 0ull, a1 = 0ull, a2 = 0ull, a3 = 0ull;
        #pragma unroll
        for (int c = 0; c < 4; ++c) {
            if      (c == 0) { CP_WAIT(3); }
            else if (c == 1) { CP_WAIT(2); }
            else if (c == 2) { CP_WAIT(1); }
            else             { CP_WAIT(0); }
            __syncwarp();
            const float* Hc = Swh + ((krow0 + (c << 4)) << 4);
            const ull*   Wc = WDu + ((krow0 + (c << 4)) << 4);
            #pragma unroll
            for (int kk = 0; kk < 16; ++kk) {
                ull h2 = *(const ull*)(Hc + (kk << 4) + (bg << 1));
                ulonglong2 w0 = *(const ulonglong2*)(Wc + (kk << 4) + (cq << 2));
                ulonglong2 w1 = *(const ulonglong2*)(Wc + (kk << 4) + (cq << 2) + 2);
                a0 = ffma2_(h2, w0.x, a0);
                a1 = ffma2_(h2, w0.y, a1);
                a2 = ffma2_(h2, w1.x, a2);
                a3 = ffma2_(h2, w1.y, a3);
            }
        }
        {   // partials: zred[ws][16 c][16 b] as u64 pairs
            ull* zru = (ull*)zred;
            int base = ((wid << 4) + (cq << 2)) << 3;
            zru[base + bg]      = a0;
            zru[base + 8 + bg]  = a1;
            zru[base + 16 + bg] = a2;
            zru[base + 24 + bg] = a3;
        }
        __syncthreads();

        // ---- gates + state update (64 threads: jj 0..3, b 0..15) ----
        if (tid < 64) {
            int b = tid & 15, jj = tid >> 4;
            float g[4];
            #pragma unroll
            for (int gate = 0; gate < 4; ++gate) {
                int c = (gate << 2) + jj;
                float s = zxs[(c << 4) + b];
                #pragma unroll
                for (int ks = 0; ks < 8; ++ks) s += zred[(((ks << 4) + c) << 4) + b];
                g[gate] = s;
            }
            float i_ = fsig_(g[0]);
            float jt = ftanh_(g[1]);
            float f_ = fsig_(g[2] + 1.f);
            float o_ = fsig_(g[3]);
            float cold = cs[tid];
            float cnew = cold * f_ + i_ * jt;
            float hnew = ftanh_(cnew) * o_;
            bool m = t < ls[b];
            int hd = hd0 + jj;
            float hold = Swh[(hd << 4) + b];
            cs[tid] = m ? cnew : cold;
            g_hT[(((grp << 1) + ((t + 1) & 1)) << 13) + (hd << 4) + b] = m ? hnew : hold;
            g_Y[((size_t)(t << 9) + hd) * 32 + (grp << 4) + b] = m ? hnew : 0.f;
        }
        __syncthreads();

        // ---- group barrier: release-arrive + acquire-poll, monotonic ----
        if (tid == 0) {
            asm volatile("red.release.gpu.global.add.u32 [%0], %1;"
                         :: "l"(barp), "r"(1u) : "memory");
            unsigned target = (unsigned)(t + 1) * BPG;
            unsigned v;
            do {
                asm volatile("ld.acquire.gpu.global.u32 %0, [%1];"
                             : "=r"(v) : "l"(barp) : "memory");
            } while (v < target);
        }
        __syncthreads();
    }
}

// ================================================================================
// Phase C: projection + masked xent. one block per t
// ================================================================================
#define LS_YS   0
#define LS_PW   16384
#define LS_LG   (16384 + 25600)
#define LOSS_SMEM ((LS_LG + 1600) * 4)

__global__ void __launch_bounds__(256, 1)
loss_kernel(const int* __restrict__ a, const int* __restrict__ lengths,
            const float* __restrict__ pW, const float* __restrict__ pb)
{
    extern __shared__ float lsm[];
    float* ys  = lsm + LS_YS;
    float* pWs = lsm + LS_PW;
    float* lg  = lsm + LS_LG;
    const int t = blockIdx.x;
    const int tid = threadIdx.x;

    {
        const float4* src = (const float4*)(g_Y + (size_t)t * (H_ * B_));
        float4* dst = (float4*)ys;
        #pragma unroll
        for (int i = 0; i < 16; ++i) dst[tid + i * 256] = src[tid + i * 256];
        const float4* ps = (const float4*)pW;
        float4* pd = (float4*)pWs;
        #pragma unroll
        for (int i = 0; i < 25; ++i) pd[tid + i * 256] = ps[tid + i * 256];
    }
    __syncthreads();

    {
        int b = tid & 31, l0 = tid >> 5;
        for (int l = l0; l < 50; l += 8) {
            float s = __ldg(&pb[l]);
            #pragma unroll 8
            for (int h = 0; h < 512; ++h) s += ys[h * 32 + b] * pWs[h * 50 + l];
            lg[l * 32 + b] = fmaxf(s, 0.f);
        }
    }
    __syncthreads();

    if (tid < 32) {
        int b = tid;
        if (t < __ldg(&lengths[b])) {
            float mx = lg[b];
            #pragma unroll
            for (int l = 1; l < 50; ++l) mx = fmaxf(mx, lg[l * 32 + b]);
            float se = 0.f;
            #pragma unroll
            for (int l = 0; l < 50; ++l) se += expf(lg[l * 32 + b] - mx);
            float lse = logf(se) + mx;
            int lab = __ldg(&a[(b << 9) + t]);
            atomicAdd(&g_acc[b], lse - lg[lab * 32 + b]);
        }
    }
}

__global__ void final_kernel(const int* __restrict__ lengths, float* __restrict__ out) {
    if (threadIdx.x == 0) {
        float s = 0.f;
        for (int b = 0; b < B_; ++b) s += g_acc[b] / (float)lengths[b];
        out[0] = s * (1.f / (float)B_);
    }
}

// ---------------- launch ----------------------------------------------------------
extern "C" void kernel_launch(void* const* d_in, const int* in_sizes, int n_in,
                              void* d_out, int out_size) {
    const int*   q       = (const int*)d_in[0];
    const int*   a       = (const int*)d_in[1];
    const int*   lengths = (const int*)d_in[2];
    const float* we      = (const float*)d_in[3];
    const float* W       = (const float*)d_in[4];
    const float* bvec    = (const float*)d_in[5];
    const float* pW      = (const float*)d_in[6];
    const float* pb      = (const float*)d_in[7];
    float* out = (float*)d_out;

    cudaFuncSetAttribute(zx_kernel, cudaFuncAttributeMaxDynamicSharedMemorySize, ZX_SMEM);
    cudaFuncSetAttribute(lstm_kernel, cudaFuncAttributeMaxDynamicSharedMemorySize, SMEM_TOTAL);
    cudaFuncSetAttribute(loss_kernel, cudaFuncAttributeMaxDynamicSharedMemorySize, LOSS_SMEM);

    zx_kernel<<<T_ * 4, 256, ZX_SMEM>>>(q, we, W, bvec);
    lstm_kernel<<<NBLK, NT, SMEM_TOTAL>>>(lengths, W);
    loss_kernel<<<T_, 256, LOSS_SMEM>>>(a, lengths, pW, pb);
    final_kernel<<<1, 32>>>(lengths, out);
}